// round 12
// baseline (speedup 1.0000x reference)
#include <cuda_runtime.h>
#include <cuda_bf16.h>
#include <cstdint>

// ============================================================================
// QuadraticSplineStack: 3 stacked quadratic splines (128, 64, 32 knots),
// 5000 genes, 4M elements.
//
// R12: eval = exact R11 (persistent 1184 CTAs, 2 elem/chunk, __ldg probes,
// direction-locked walk, fused log, streaming I/O).
// Precompute: build per-bin records ONCE in smem (one RCP/bin), range-fill a
// smem bin-index byte array, then emit the cell table with lane c -> cell c
// COALESCED STG.128 (4 wavefronts/instr instead of ~32 for scattered emission;
// R7's version lost because it recomputed RCP per cell, +1.1M MUFU).
// ============================================================================

#define MAX_GENES 5000
#define PARAMS_PER_GENE 445

#define NBINS0 127
#define NBINS1 63
#define NBINS2 31
#define CELLS_PER_GENE (2*NBINS0 + 2*NBINS1 + 2*NBINS2)   // 442

struct __align__(16) Rec {
    float    bl;       // bin left location (exact f32)
    unsigned invw_lh;  // low16: invw * 16384/nb ; high16: lh * 16384
    float    d;        // rh - lh
    float    lc;       // left cdf
};

__device__ Rec g_cell[MAX_GENES * CELLS_PER_GENE];

// ---------------------------------------------------------------------------
// warp helpers
// ---------------------------------------------------------------------------
__device__ __forceinline__ float warp_incl_scan(float v, int lane) {
#pragma unroll
    for (int o = 1; o < 32; o <<= 1) {
        float t = __shfl_up_sync(0xffffffffu, v, o);
        if (lane >= o) v += t;
    }
    return v;
}
__device__ __forceinline__ float warp_sum(float v) {
#pragma unroll
    for (int o = 16; o; o >>= 1) v += __shfl_xor_sync(0xffffffffu, v, o);
    return v;
}

// ---------------------------------------------------------------------------
// Precompute: one warp per (gene, transform). 8 warps / 256-thread block.
// ---------------------------------------------------------------------------
__global__ void __launch_bounds__(256) precompute_kernel(const float* __restrict__ unnorm,
                                                         int nGenes) {
    __shared__ float sbuf[8][512];            // sw, sl, se, sc (128 each)
    __shared__ uint4 srec[8][128];            // per-bin packed records
    __shared__ unsigned char sbin[8][256];    // cell -> bin index

    const int wib  = threadIdx.x >> 5;
    const int lane = threadIdx.x & 31;
    const int wid  = blockIdx.x * 8 + wib;
    const int g    = wid / 3;
    const int t    = wid - g * 3;
    if (g >= nGenes) return;

    const int NS[3]   = {128, 64, 32};
    const int POFF[3] = {0, 255, 382};
    const int COFF[3] = {0, 2 * NBINS0, 2 * NBINS0 + 2 * NBINS1};

    const int n  = NS[t];
    const int nb = n - 1;
    const int M  = 2 * nb;
    const float invw_scale = 16384.f / (float)nb;

    const float* uh = unnorm + (long)g * PARAMS_PER_GENE + POFF[t];
    const float* uw = uh + n;

    float* sw = sbuf[wib];
    float* sl = sw + 128;
    float* se = sl + 128;
    float* sc = se + 128;

    // softmax widths (no max-subtraction: |uw| is small, shift-invariant)
    float s = 0.f;
    for (int i = lane; i < nb; i += 32) {
        float e = __expf(uw[i]);
        sw[i] = e;
        s += e;
    }
    s = warp_sum(s);
    float invs = 1.0f / s;
    for (int i = lane; i < nb; i += 32) sw[i] *= invs;
    __syncwarp();

    // inclusive scan of widths -> sl
    float carry = 0.f;
    for (int base = 0; base < nb; base += 32) {
        int i = base + lane;
        float v = (i < nb) ? sw[i] : 0.f;
        float scn = warp_incl_scan(v, lane);
        if (i < nb) sl[i] = scn + carry;
        carry += __shfl_sync(0xffffffffu, scn, 31);
    }

    // heights: exp, trapezoid area, normalize
    for (int i = lane; i < n; i += 32) se[i] = __expf(uh[i]);
    __syncwarp();
    float a = 0.f;
    for (int i = lane; i < nb; i += 32) a += 0.5f * (se[i] + se[i + 1]) * sw[i];
    a = warp_sum(a);
    float inva = 1.0f / a;
    for (int i = lane; i < n; i += 32) se[i] *= inva;
    __syncwarp();

    // inclusive scan of cdf terms -> sc
    carry = 0.f;
    for (int base = 0; base < nb; base += 32) {
        int i = base + lane;
        float v = (i < nb) ? 0.5f * (se[i] + se[i + 1]) * sw[i] : 0.f;
        float scn = warp_incl_scan(v, lane);
        if (i < nb) sc[i] = scn + carry;
        carry += __shfl_sync(0xffffffffu, scn, 31);
    }
    __syncwarp();

    // pass B: per-bin record into smem (ONE rcp per bin) + bin-index range fill
    const float Mf = (float)M;
    for (int b = lane; b < nb; b += 32) {
        float blv = b ? sl[b - 1] : 0.f;
        float lh  = se[b];

        Rec r;
        r.bl = blv;
        unsigned iq = (unsigned)fminf(rintf((1.f / sw[b]) * invw_scale), 65535.f);
        unsigned lq = (unsigned)fminf(rintf(lh * 16384.f), 65535.f);
        r.invw_lh = iq | (lq << 16);
        r.d  = se[b + 1] - lh;
        r.lc = b ? sc[b - 1] : 0.f;
        srec[wib][b] = *reinterpret_cast<uint4*>(&r);

        int c0 = b ? (int)ceilf(blv * Mf - 0.5f) : 0;
        int c1 = (b == nb - 1) ? M : (int)ceilf(sl[b] * Mf - 0.5f);
        c0 = (c0 < 0) ? 0 : c0;
        c1 = (c1 > M) ? M : c1;
        for (int c = c0; c < c1; ++c) sbin[wib][c] = (unsigned char)b;
    }
    __syncwarp();

    // pass C: coalesced emission — lane c copies srec[sbin[c]] to cell c
    Rec* crec = g_cell + (long)g * CELLS_PER_GENE + COFF[t];
    for (int c = lane; c < M; c += 32) {
        reinterpret_cast<uint4*>(crec)[c] = srec[wib][sbin[wib][c]];
    }
}

// ---------------------------------------------------------------------------
// Eval: persistent grid-stride, 2 elements per chunk, direction-locked walk.
// (exact R11 version — best measured)
// ---------------------------------------------------------------------------
template<int NB>
__device__ __forceinline__ float apply_t(const Rec* __restrict__ cell,
                                         float v, float& fprod) {
    constexpr int   M       = 2 * NB;
    constexpr float INVW_SC = (float)NB / 16384.f;
    constexpr float LH_SC   = 1.f / 16384.f;

    int c = (int)(v * (float)M);
    c = (c < 0) ? 0 : ((c > M - 1) ? (M - 1) : c);

    uint4 u = __ldg(reinterpret_cast<const uint4*>(cell + c));
    float bl    = __uint_as_float(u.x);
    float invw  = (float)(u.y & 0xFFFFu) * INVW_SC;
    float alpha = (v - bl) * invw;

    // direction-locked walk: guaranteed termination under quantized invw
    if (alpha < 0.f || alpha >= 1.f) {
        const int  dir   = (alpha >= 1.f) ? 1 : -1;
        const bool right = (dir > 0);
        for (;;) {
            int nc = c + dir;
            if (nc < 0 || nc > M - 1) break;
            c = nc;
            u = __ldg(reinterpret_cast<const uint4*>(cell + c));
            bl    = __uint_as_float(u.x);
            invw  = (float)(u.y & 0xFFFFu) * INVW_SC;
            alpha = (v - bl) * invw;
            bool cont = right ? (alpha >= 1.f) : (alpha < 0.f);
            if (!cont) break;
        }
    }

    float lh = (float)(u.y >> 16) * LH_SC;
    float d  = __uint_as_float(u.z);
    float lc = __uint_as_float(u.w);

    fprod *= fmaf(d, alpha, lh);
    float out = fmaf(v - bl, fmaf(0.5f * d, alpha, lh), lc);
    return fminf(fmaxf(out, 0.f), 1.f);
}

__global__ void __launch_bounds__(256) spline_eval_kernel(
    const float* __restrict__ x,
    const int* __restrict__ gix,
    float* __restrict__ out,
    float* __restrict__ lad_out,
    int N)
{
    const long nChunks = N >> 1;                       // float2 chunks
    const long stride  = (long)gridDim.x * blockDim.x;

    for (long t = (long)blockIdx.x * blockDim.x + threadIdx.x;
         t < nChunks; t += stride) {

        float2 xv = __ldcs(reinterpret_cast<const float2*>(x) + t);
        int2   gv = __ldcs(reinterpret_cast<const int2*>(gix) + t);

        float fp0 = 1.f, fp1 = 1.f;
        float v0 = xv.x, v1 = xv.y;
        const Rec* cb0 = g_cell + (long)gv.x * CELLS_PER_GENE;
        const Rec* cb1 = g_cell + (long)gv.y * CELLS_PER_GENE;

        v0 = apply_t<NBINS0>(cb0, v0, fp0);
        v1 = apply_t<NBINS0>(cb1, v1, fp1);
        v0 = apply_t<NBINS1>(cb0 + 2 * NBINS0, v0, fp0);
        v1 = apply_t<NBINS1>(cb1 + 2 * NBINS0, v1, fp1);
        v0 = apply_t<NBINS2>(cb0 + 2 * (NBINS0 + NBINS1), v0, fp0);
        v1 = apply_t<NBINS2>(cb1 + 2 * (NBINS0 + NBINS1), v1, fp1);

        __stcs(reinterpret_cast<float2*>(out) + t,     make_float2(v0, v1));
        __stcs(reinterpret_cast<float2*>(lad_out) + t, make_float2(__logf(fp0), __logf(fp1)));
    }

    // odd tail element (N odd): handled by one thread
    if ((N & 1) && blockIdx.x == 0 && threadIdx.x == 0) {
        long i = (long)N - 1;
        float v  = __ldcs(x + i);
        int   g  = __ldcs(gix + i);
        float fp = 1.f;
        const Rec* cb = g_cell + (long)g * CELLS_PER_GENE;
        v = apply_t<NBINS0>(cb, v, fp);
        v = apply_t<NBINS1>(cb + 2 * NBINS0, v, fp);
        v = apply_t<NBINS2>(cb + 2 * (NBINS0 + NBINS1), v, fp);
        __stcs(out + i, v);
        __stcs(lad_out + i, __logf(fp));
    }
}

// ---------------------------------------------------------------------------
// launch
// ---------------------------------------------------------------------------
extern "C" void kernel_launch(void* const* d_in, const int* in_sizes, int n_in,
                              void* d_out, int out_size) {
    const float* x      = (const float*)d_in[0];
    const int*   gix    = (const int*)d_in[1];
    const float* unnorm = (const float*)d_in[2];

    int N = in_sizes[0];
    int nGenes = in_sizes[2] / PARAMS_PER_GENE;
    if (nGenes > MAX_GENES) nGenes = MAX_GENES;

    float* out = (float*)d_out;
    float* lad = out + N;

    int nWarps = nGenes * 3;
    precompute_kernel<<<(nWarps + 7) / 8, 256>>>(unnorm, nGenes);

    // persistent: 8 CTAs/SM x 148 SMs
    int evalGrid = 148 * 8;
    long nChunks = N >> 1;
    long maxGrid = (nChunks + 255) / 256;
    if (evalGrid > maxGrid) evalGrid = (int)maxGrid;
    if (evalGrid < 1) evalGrid = 1;
    spline_eval_kernel<<<evalGrid, 256>>>(x, gix, out, lad, N);
}

// round 15
// speedup vs baseline: 1.0265x; 1.0265x over previous
#include <cuda_runtime.h>
#include <cuda_bf16.h>
#include <cstdint>

// ============================================================================
// QuadraticSplineStack: 3 stacked quadratic splines (128, 64, 32 knots),
// 5000 genes, 4M elements.
//
// R13 = R11 (best: persistent eval, __ldg probes, direction-locked walk,
// fused log, R3-style direct range-fill precompute) plus:
//  - precompute: uh-exp pass hoisted before width reductions (overlap the
//    two DRAM param-load rounds in one latency window)
//  - stage-2 cell table densified to M = 4*nb (miss 12.5% -> 6%, +5MB table)
// ============================================================================

#define MAX_GENES 5000
#define PARAMS_PER_GENE 445

#define NBINS0 127
#define NBINS1 63
#define NBINS2 31
#define MCELL0 (2*NBINS0)   // 254
#define MCELL1 (2*NBINS1)   // 126
#define MCELL2 (4*NBINS2)   // 124
#define CELLS_PER_GENE (MCELL0 + MCELL1 + MCELL2)   // 504

struct __align__(16) Rec {
    float    bl;       // bin left location (exact f32)
    unsigned invw_lh;  // low16: invw * 16384/nb ; high16: lh * 16384
    float    d;        // rh - lh
    float    lc;       // left cdf
};

__device__ Rec g_cell[MAX_GENES * CELLS_PER_GENE];

// ---------------------------------------------------------------------------
// warp helpers
// ---------------------------------------------------------------------------
__device__ __forceinline__ float warp_incl_scan(float v, int lane) {
#pragma unroll
    for (int o = 1; o < 32; o <<= 1) {
        float t = __shfl_up_sync(0xffffffffu, v, o);
        if (lane >= o) v += t;
    }
    return v;
}
__device__ __forceinline__ float warp_sum(float v) {
#pragma unroll
    for (int o = 16; o; o >>= 1) v += __shfl_xor_sync(0xffffffffu, v, o);
    return v;
}

// ---------------------------------------------------------------------------
// Precompute: one warp per (gene, transform). 8 warps / 256-thread block.
// ---------------------------------------------------------------------------
__global__ void __launch_bounds__(256) precompute_kernel(const float* __restrict__ unnorm,
                                                         int nGenes) {
    __shared__ float sbuf[8][512];

    const int wib  = threadIdx.x >> 5;
    const int lane = threadIdx.x & 31;
    const int wid  = blockIdx.x * 8 + wib;
    const int g    = wid / 3;
    const int t    = wid - g * 3;
    if (g >= nGenes) return;

    const int NS[3]   = {128, 64, 32};
    const int POFF[3] = {0, 255, 382};
    const int COFF[3] = {0, MCELL0, MCELL0 + MCELL1};
    const int CMUL[3] = {2, 2, 4};

    const int n  = NS[t];
    const int nb = n - 1;
    const int M  = CMUL[t] * nb;
    const float invw_scale = 16384.f / (float)nb;

    const float* uh = unnorm + (long)g * PARAMS_PER_GENE + POFF[t];
    const float* uw = uh + n;

    float* sw = sbuf[wib];
    float* sl = sw + 128;
    float* se = sl + 128;
    float* sc = se + 128;

    // load+exp both param rows first (two independent DRAM rounds overlap)
    float s = 0.f;
    for (int i = lane; i < nb; i += 32) {
        float e = __expf(uw[i]);
        sw[i] = e;
        s += e;
    }
    for (int i = lane; i < n; i += 32) se[i] = __expf(uh[i]);

    // softmax widths (shift-invariant; |uw| small)
    s = warp_sum(s);
    float invs = 1.0f / s;
    for (int i = lane; i < nb; i += 32) sw[i] *= invs;
    __syncwarp();

    // inclusive scan of widths -> sl
    float carry = 0.f;
    for (int base = 0; base < nb; base += 32) {
        int i = base + lane;
        float v = (i < nb) ? sw[i] : 0.f;
        float scn = warp_incl_scan(v, lane);
        if (i < nb) sl[i] = scn + carry;
        carry += __shfl_sync(0xffffffffu, scn, 31);
    }
    __syncwarp();

    // heights: trapezoid area, normalize
    float a = 0.f;
    for (int i = lane; i < nb; i += 32) a += 0.5f * (se[i] + se[i + 1]) * sw[i];
    a = warp_sum(a);
    float inva = 1.0f / a;
    for (int i = lane; i < n; i += 32) se[i] *= inva;
    __syncwarp();

    // inclusive scan of cdf terms -> sc
    carry = 0.f;
    for (int base = 0; base < nb; base += 32) {
        int i = base + lane;
        float v = (i < nb) ? 0.5f * (se[i] + se[i + 1]) * sw[i] : 0.f;
        float scn = warp_incl_scan(v, lane);
        if (i < nb) sc[i] = scn + carry;
        carry += __shfl_sync(0xffffffffu, scn, 31);
    }
    __syncwarp();

    // emit cell records: bin b covers cells [f(bl), f(br)), f(t) = ceil(t*M - 0.5)
    Rec* crec = g_cell + (long)g * CELLS_PER_GENE + COFF[t];
    const float Mf = (float)M;
    for (int b = lane; b < nb; b += 32) {
        float blv = b ? sl[b - 1] : 0.f;
        float lh  = se[b];

        Rec r;
        r.bl = blv;
        unsigned iq = (unsigned)fminf(rintf((1.f / sw[b]) * invw_scale), 65535.f);
        unsigned lq = (unsigned)fminf(rintf(lh * 16384.f), 65535.f);
        r.invw_lh = iq | (lq << 16);
        r.d  = se[b + 1] - lh;
        r.lc = b ? sc[b - 1] : 0.f;

        int c0 = b ? (int)ceilf(blv * Mf - 0.5f) : 0;
        int c1 = (b == nb - 1) ? M : (int)ceilf(sl[b] * Mf - 0.5f);
        c0 = (c0 < 0) ? 0 : c0;
        c1 = (c1 > M) ? M : c1;
        for (int c = c0; c < c1; ++c) crec[c] = r;
    }
}

// ---------------------------------------------------------------------------
// Eval: persistent grid-stride, 2 elements per chunk, direction-locked walk.
// ---------------------------------------------------------------------------
template<int NB, int M>
__device__ __forceinline__ float apply_t(const Rec* __restrict__ cell,
                                         float v, float& fprod) {
    constexpr float INVW_SC = (float)NB / 16384.f;
    constexpr float LH_SC   = 1.f / 16384.f;

    int c = (int)(v * (float)M);
    c = (c < 0) ? 0 : ((c > M - 1) ? (M - 1) : c);

    uint4 u = __ldg(reinterpret_cast<const uint4*>(cell + c));
    float bl    = __uint_as_float(u.x);
    float invw  = (float)(u.y & 0xFFFFu) * INVW_SC;
    float alpha = (v - bl) * invw;

    // direction-locked walk: guaranteed termination under quantized invw
    if (alpha < 0.f || alpha >= 1.f) {
        const int  dir   = (alpha >= 1.f) ? 1 : -1;
        const bool right = (dir > 0);
        for (;;) {
            int nc = c + dir;
            if (nc < 0 || nc > M - 1) break;
            c = nc;
            u = __ldg(reinterpret_cast<const uint4*>(cell + c));
            bl    = __uint_as_float(u.x);
            invw  = (float)(u.y & 0xFFFFu) * INVW_SC;
            alpha = (v - bl) * invw;
            bool cont = right ? (alpha >= 1.f) : (alpha < 0.f);
            if (!cont) break;
        }
    }

    float lh = (float)(u.y >> 16) * LH_SC;
    float d  = __uint_as_float(u.z);
    float lc = __uint_as_float(u.w);

    fprod *= fmaf(d, alpha, lh);
    float out = fmaf(v - bl, fmaf(0.5f * d, alpha, lh), lc);
    return fminf(fmaxf(out, 0.f), 1.f);
}

__global__ void __launch_bounds__(256) spline_eval_kernel(
    const float* __restrict__ x,
    const int* __restrict__ gix,
    float* __restrict__ out,
    float* __restrict__ lad_out,
    int N)
{
    const long nChunks = N >> 1;                       // float2 chunks
    const long stride  = (long)gridDim.x * blockDim.x;

    for (long t = (long)blockIdx.x * blockDim.x + threadIdx.x;
         t < nChunks; t += stride) {

        float2 xv = __ldcs(reinterpret_cast<const float2*>(x) + t);
        int2   gv = __ldcs(reinterpret_cast<const int2*>(gix) + t);

        float fp0 = 1.f, fp1 = 1.f;
        float v0 = xv.x, v1 = xv.y;
        const Rec* cb0 = g_cell + (long)gv.x * CELLS_PER_GENE;
        const Rec* cb1 = g_cell + (long)gv.y * CELLS_PER_GENE;

        v0 = apply_t<NBINS0, MCELL0>(cb0, v0, fp0);
        v1 = apply_t<NBINS0, MCELL0>(cb1, v1, fp1);
        v0 = apply_t<NBINS1, MCELL1>(cb0 + MCELL0, v0, fp0);
        v1 = apply_t<NBINS1, MCELL1>(cb1 + MCELL0, v1, fp1);
        v0 = apply_t<NBINS2, MCELL2>(cb0 + MCELL0 + MCELL1, v0, fp0);
        v1 = apply_t<NBINS2, MCELL2>(cb1 + MCELL0 + MCELL1, v1, fp1);

        __stcs(reinterpret_cast<float2*>(out) + t,     make_float2(v0, v1));
        __stcs(reinterpret_cast<float2*>(lad_out) + t, make_float2(__logf(fp0), __logf(fp1)));
    }

    // odd tail element (N odd): handled by one thread
    if ((N & 1) && blockIdx.x == 0 && threadIdx.x == 0) {
        long i = (long)N - 1;
        float v  = __ldcs(x + i);
        int   g  = __ldcs(gix + i);
        float fp = 1.f;
        const Rec* cb = g_cell + (long)g * CELLS_PER_GENE;
        v = apply_t<NBINS0, MCELL0>(cb, v, fp);
        v = apply_t<NBINS1, MCELL1>(cb + MCELL0, v, fp);
        v = apply_t<NBINS2, MCELL2>(cb + MCELL0 + MCELL1, v, fp);
        __stcs(out + i, v);
        __stcs(lad_out + i, __logf(fp));
    }
}

// ---------------------------------------------------------------------------
// launch
// ---------------------------------------------------------------------------
extern "C" void kernel_launch(void* const* d_in, const int* in_sizes, int n_in,
                              void* d_out, int out_size) {
    const float* x      = (const float*)d_in[0];
    const int*   gix    = (const int*)d_in[1];
    const float* unnorm = (const float*)d_in[2];

    int N = in_sizes[0];
    int nGenes = in_sizes[2] / PARAMS_PER_GENE;
    if (nGenes > MAX_GENES) nGenes = MAX_GENES;

    float* out = (float*)d_out;
    float* lad = out + N;

    int nWarps = nGenes * 3;
    precompute_kernel<<<(nWarps + 7) / 8, 256>>>(unnorm, nGenes);

    // persistent: 8 CTAs/SM x 148 SMs
    int evalGrid = 148 * 8;
    long nChunks = N >> 1;
    long maxGrid = (nChunks + 255) / 256;
    if (evalGrid > maxGrid) evalGrid = (int)maxGrid;
    if (evalGrid < 1) evalGrid = 1;
    spline_eval_kernel<<<evalGrid, 256>>>(x, gix, out, lad, N);
}